// round 1
// baseline (speedup 1.0000x reference)
#include <cuda_runtime.h>

// ---------------------------------------------------------------------------
// Swin shifted-window attention (W-MCA, SW type), fp32 baseline.
// x,b: (2,256,256,192) f32. P=8 windows, SHIFT=4, 6 heads x 32 dim.
// ---------------------------------------------------------------------------

#define BATCH   2
#define IMG     256
#define C       192
#define PW      8
#define SHIFT   4
#define HEADS   6
#define HD      32
#define NWSIDE  32              // windows per side
#define NW      (NWSIDE*NWSIDE) // 1024 windows per image
#define PP      64              // tokens per window
#define NTOK    (BATCH*NW*PP)   // 131072 tokens
#define SCALE   0.17677669529663687f

// Scratch (static device allocations; no runtime malloc)
__device__ float g_q [NTOK * C];
__device__ float g_k [NTOK * C];
__device__ float g_v [NTOK * C];
__device__ float g_ao[NTOK * C];

// token index -> source/dest pixel row offset (in floats) applying the
// cyclic shift and window partition (same map for gather and scatter).
__device__ __forceinline__ int tok_to_pix_row(int tok) {
    int bi  = tok >> 16;
    int rr  = tok & 65535;
    int win = rr >> 6, pix = rr & 63;
    int wy = win >> 5, wx = win & 31;
    int py = pix >> 3, px = pix & 7;
    int hh = (wy * 8 + py + SHIFT) & 255;
    int ww = (wx * 8 + px + SHIFT) & 255;
    return ((bi << 8 | hh) << 8 | ww) * C;
}

// ---------------------------------------------------------------------------
// Kernel 1: QKV projection, fused with roll+window gather on the input rows.
//   q (cols   0..191) = b  @ w_qkv_b[0:192].T   + b_qkv_b[0:192]
//   k (cols 192..383) = x  @ w_qkv [192:384].T  + b_qkv[192:384]
//   v (cols 384..575) = x  @ w_qkv [384:576].T  + b_qkv[384:576]
// grid: (9 n-tiles of 64, 2048 m-tiles of 64), 256 threads, 4x4 reg tile.
// ---------------------------------------------------------------------------
__global__ __launch_bounds__(256) void qkv_kernel(
    const float* __restrict__ x, const float* __restrict__ b,
    const float* __restrict__ w_qkv,   const float* __restrict__ b_qkv,
    const float* __restrict__ w_qkv_b, const float* __restrict__ b_qkv_b)
{
    const int nt = blockIdx.x;      // 0..8
    const int mt = blockIdx.y;      // 0..2047
    const int region = nt / 3;      // 0=q, 1=k, 2=v
    const int n0 = nt * 64;         // global output column
    const int m0 = mt * 64;         // token tile base

    const float* src = (region == 0) ? b        : x;
    const float* wgt = (region == 0) ? w_qkv_b  : w_qkv;
    const float* bia = (region == 0) ? b_qkv_b  : b_qkv;
    float*       dst = (region == 0) ? g_q : (region == 1) ? g_k : g_v;
    const int coloff = region * 192;

    __shared__ float As[16][68];    // [k][m]
    __shared__ float Bs[16][68];    // [k][n]

    const int tid = threadIdx.x;
    const int tx  = tid & 15;       // n quadrant
    const int ty  = tid >> 4;       // m quadrant

    // loader indices
    const int lm = tid >> 2;            // row within tile (token / weight row)
    const int lk = (tid & 3) * 4;       // k offset {0,4,8,12}
    const float* arow = src + tok_to_pix_row(m0 + lm);
    const float* wrow = wgt + (size_t)(n0 + lm) * C;

    float acc[4][4] = {};
    for (int k0 = 0; k0 < C; k0 += 16) {
        float4 av = *reinterpret_cast<const float4*>(arow + k0 + lk);
        float4 bv = *reinterpret_cast<const float4*>(wrow + k0 + lk);
        __syncthreads();
        As[lk+0][lm] = av.x; As[lk+1][lm] = av.y;
        As[lk+2][lm] = av.z; As[lk+3][lm] = av.w;
        Bs[lk+0][lm] = bv.x; Bs[lk+1][lm] = bv.y;
        Bs[lk+2][lm] = bv.z; Bs[lk+3][lm] = bv.w;
        __syncthreads();
        #pragma unroll
        for (int k = 0; k < 16; ++k) {
            float4 a4 = *reinterpret_cast<const float4*>(&As[k][ty * 4]);
            float4 b4 = *reinterpret_cast<const float4*>(&Bs[k][tx * 4]);
            acc[0][0] += a4.x*b4.x; acc[0][1] += a4.x*b4.y; acc[0][2] += a4.x*b4.z; acc[0][3] += a4.x*b4.w;
            acc[1][0] += a4.y*b4.x; acc[1][1] += a4.y*b4.y; acc[1][2] += a4.y*b4.z; acc[1][3] += a4.y*b4.w;
            acc[2][0] += a4.z*b4.x; acc[2][1] += a4.z*b4.y; acc[2][2] += a4.z*b4.z; acc[2][3] += a4.z*b4.w;
            acc[3][0] += a4.w*b4.x; acc[3][1] += a4.w*b4.y; acc[3][2] += a4.w*b4.z; acc[3][3] += a4.w*b4.w;
        }
    }

    const int nc = n0 + tx * 4;
    float4 bb = make_float4(bia[nc], bia[nc+1], bia[nc+2], bia[nc+3]);
    #pragma unroll
    for (int i = 0; i < 4; ++i) {
        int m = m0 + ty * 4 + i;
        float4 o = make_float4(acc[i][0] + bb.x, acc[i][1] + bb.y,
                               acc[i][2] + bb.z, acc[i][3] + bb.w);
        *reinterpret_cast<float4*>(dst + (size_t)m * C + (nc - coloff)) = o;
    }
}

// ---------------------------------------------------------------------------
// Kernel 2: per-(window, head) attention.
// grid: (2048 windows incl. batch, 6 heads), 128 threads.
// Each thread owns half a query row (32 key columns).
// ---------------------------------------------------------------------------
__global__ __launch_bounds__(128) void attn_kernel(const float* __restrict__ rel_params)
{
    const int wg   = blockIdx.x;        // batch*window, 0..2047
    const int head = blockIdx.y;
    const int win  = wg & 1023;
    const int wy   = win >> 5, wx = win & 31;
    const bool maskY = (wy == NWSIDE - 1);
    const bool maskX = (wx == NWSIDE - 1);

    __shared__ float Qs[64][36];
    __shared__ float Ks[64][36];
    __shared__ float Vs[64][36];
    __shared__ float Ps[64][65];
    __shared__ float rel_s[225];

    const int tid = threadIdx.x;
    const size_t base = (size_t)wg * 64 * C + head * HD;

    for (int i = tid; i < 512; i += 128) {
        int row = i >> 3, q4 = (i & 7) * 4;
        size_t off = base + (size_t)row * C + q4;
        float4 qv = *reinterpret_cast<const float4*>(&g_q[off]);
        float4 kv = *reinterpret_cast<const float4*>(&g_k[off]);
        float4 vv = *reinterpret_cast<const float4*>(&g_v[off]);
        Qs[row][q4] = qv.x; Qs[row][q4+1] = qv.y; Qs[row][q4+2] = qv.z; Qs[row][q4+3] = qv.w;
        Ks[row][q4] = kv.x; Ks[row][q4+1] = kv.y; Ks[row][q4+2] = kv.z; Ks[row][q4+3] = kv.w;
        Vs[row][q4] = vv.x; Vs[row][q4+1] = vv.y; Vs[row][q4+2] = vv.z; Vs[row][q4+3] = vv.w;
    }
    for (int i = tid; i < 225; i += 128) rel_s[i] = rel_params[head * 225 + i];
    __syncthreads();

    const int r  = tid >> 1;            // query row 0..63
    const int c0 = (tid & 1) * 32;      // key column base {0,32}
    const int ry = r >> 3, rx = r & 7;

    // S = Q K^T
    float s[32];
    #pragma unroll
    for (int c = 0; c < 32; ++c) s[c] = 0.f;
    #pragma unroll
    for (int k = 0; k < 32; k += 4) {
        float4 q4 = *reinterpret_cast<const float4*>(&Qs[r][k]);
        #pragma unroll
        for (int c = 0; c < 32; ++c) {
            float4 k4 = *reinterpret_cast<const float4*>(&Ks[c0 + c][k]);
            s[c] += q4.x*k4.x + q4.y*k4.y + q4.z*k4.z + q4.w*k4.w;
        }
    }

    // scale + relative-position bias + shift mask
    #pragma unroll
    for (int c = 0; c < 32; ++c) {
        int col = c0 + c;
        int qy = col >> 3, qx = col & 7;
        float val = s[c] * SCALE + rel_s[(ry - qy + 7) * 15 + (rx - qx + 7)];
        bool msk = (maskY && ((ry < 4) != (qy < 4))) ||
                   (maskX && ((rx < 4) != (qx < 4)));
        s[c] = msk ? -1e30f : val;
    }

    // softmax over full row (two threads per row, paired via shfl)
    float mx = -1e30f;
    #pragma unroll
    for (int c = 0; c < 32; ++c) mx = fmaxf(mx, s[c]);
    mx = fmaxf(mx, __shfl_xor_sync(0xffffffffu, mx, 1));
    float sum = 0.f;
    #pragma unroll
    for (int c = 0; c < 32; ++c) { s[c] = __expf(s[c] - mx); sum += s[c]; }
    sum += __shfl_xor_sync(0xffffffffu, sum, 1);
    float inv = 1.f / sum;
    #pragma unroll
    for (int c = 0; c < 32; ++c) Ps[r][c0 + c] = s[c] * inv;
    __syncthreads();

    // O = P V  (each thread: 16 output dims of its row)
    const int co = (tid & 1) * 16;
    float o[16];
    #pragma unroll
    for (int c = 0; c < 16; ++c) o[c] = 0.f;
    #pragma unroll 8
    for (int j = 0; j < 64; ++j) {
        float p = Ps[r][j];
        #pragma unroll
        for (int c4 = 0; c4 < 16; c4 += 4) {
            float4 vv = *reinterpret_cast<const float4*>(&Vs[j][co + c4]);
            o[c4+0] += p * vv.x; o[c4+1] += p * vv.y;
            o[c4+2] += p * vv.z; o[c4+3] += p * vv.w;
        }
    }
    float* drow = &g_ao[base + (size_t)r * C + co];
    #pragma unroll
    for (int c4 = 0; c4 < 16; c4 += 4)
        *reinterpret_cast<float4*>(drow + c4) =
            make_float4(o[c4], o[c4+1], o[c4+2], o[c4+3]);
}

// ---------------------------------------------------------------------------
// Kernel 3: output projection (192x192) + bias, fused with window departition
// and roll-back scatter. grid: (3 n-tiles, 2048 m-tiles), 256 threads.
// ---------------------------------------------------------------------------
__global__ __launch_bounds__(256) void proj_kernel(
    const float* __restrict__ w_out, const float* __restrict__ b_out,
    float* __restrict__ out)
{
    const int nt = blockIdx.x;      // 0..2
    const int mt = blockIdx.y;      // 0..2047
    const int n0 = nt * 64;
    const int m0 = mt * 64;

    __shared__ float As[16][68];
    __shared__ float Bs[16][68];

    const int tid = threadIdx.x;
    const int tx  = tid & 15;
    const int ty  = tid >> 4;
    const int lm  = tid >> 2;
    const int lk  = (tid & 3) * 4;

    const float* arow = g_ao  + (size_t)(m0 + lm) * C;
    const float* wrow = w_out + (size_t)(n0 + lm) * C;

    float acc[4][4] = {};
    for (int k0 = 0; k0 < C; k0 += 16) {
        float4 av = *reinterpret_cast<const float4*>(arow + k0 + lk);
        float4 bv = *reinterpret_cast<const float4*>(wrow + k0 + lk);
        __syncthreads();
        As[lk+0][lm] = av.x; As[lk+1][lm] = av.y;
        As[lk+2][lm] = av.z; As[lk+3][lm] = av.w;
        Bs[lk+0][lm] = bv.x; Bs[lk+1][lm] = bv.y;
        Bs[lk+2][lm] = bv.z; Bs[lk+3][lm] = bv.w;
        __syncthreads();
        #pragma unroll
        for (int k = 0; k < 16; ++k) {
            float4 a4 = *reinterpret_cast<const float4*>(&As[k][ty * 4]);
            float4 b4 = *reinterpret_cast<const float4*>(&Bs[k][tx * 4]);
            acc[0][0] += a4.x*b4.x; acc[0][1] += a4.x*b4.y; acc[0][2] += a4.x*b4.z; acc[0][3] += a4.x*b4.w;
            acc[1][0] += a4.y*b4.x; acc[1][1] += a4.y*b4.y; acc[1][2] += a4.y*b4.z; acc[1][3] += a4.y*b4.w;
            acc[2][0] += a4.z*b4.x; acc[2][1] += a4.z*b4.y; acc[2][2] += a4.z*b4.z; acc[2][3] += a4.z*b4.w;
            acc[3][0] += a4.w*b4.x; acc[3][1] += a4.w*b4.y; acc[3][2] += a4.w*b4.z; acc[3][3] += a4.w*b4.w;
        }
    }

    const int nc = n0 + tx * 4;
    float4 bb = make_float4(b_out[nc], b_out[nc+1], b_out[nc+2], b_out[nc+3]);
    #pragma unroll
    for (int i = 0; i < 4; ++i) {
        int tok = m0 + ty * 4 + i;
        float* drow = out + tok_to_pix_row(tok) + nc;
        *reinterpret_cast<float4*>(drow) =
            make_float4(acc[i][0] + bb.x, acc[i][1] + bb.y,
                        acc[i][2] + bb.z, acc[i][3] + bb.w);
    }
}

// ---------------------------------------------------------------------------
extern "C" void kernel_launch(void* const* d_in, const int* in_sizes, int n_in,
                              void* d_out, int out_size)
{
    const float* x        = (const float*)d_in[0];
    const float* b        = (const float*)d_in[1];
    const float* w_qkv    = (const float*)d_in[2];
    const float* b_qkv    = (const float*)d_in[3];
    const float* w_qkv_b  = (const float*)d_in[4];
    const float* b_qkv_b  = (const float*)d_in[5];
    const float* rel      = (const float*)d_in[6];
    const float* w_out    = (const float*)d_in[7];
    const float* b_out    = (const float*)d_in[8];
    float* out = (float*)d_out;

    qkv_kernel<<<dim3(9, 2048), 256>>>(x, b, w_qkv, b_qkv, w_qkv_b, b_qkv_b);
    attn_kernel<<<dim3(2048, 6), 128>>>(rel);
    proj_kernel<<<dim3(3, 2048), 256>>>(w_out, b_out, out);
}

// round 2
// speedup vs baseline: 3.4559x; 3.4559x over previous
#include <cuda_runtime.h>
#include <cuda_fp16.h>
#include <cstdint>

// ---------------------------------------------------------------------------
// Swin shifted-window attention, fp16 tensor-core version (mma.sync HMMA).
// ---------------------------------------------------------------------------

#define C       192
#define SHIFT   4
#define NTOK    (2*1024*64)      // 131072 tokens
#define SCALE   0.17677669529663687f

// fp16 scratch + pre-converted weights (static device allocations)
__device__ __half g_q  [NTOK * C];
__device__ __half g_k  [NTOK * C];
__device__ __half g_v  [NTOK * C];
__device__ __half g_ao [NTOK * C];
__device__ __half gw_qkv [576 * C];
__device__ __half gw_qkvb[576 * C];
__device__ __half gw_out [C * C];

// token index -> pixel row offset (floats/halves count = elements) applying
// cyclic shift + window partition (same map for gather and scatter).
__device__ __forceinline__ int tok_to_pix_row(int tok) {
    int bi  = tok >> 16;
    int rr  = tok & 65535;
    int win = rr >> 6, pix = rr & 63;
    int wy = win >> 5, wx = win & 31;
    int py = pix >> 3, px = pix & 7;
    int hh = (wy * 8 + py + SHIFT) & 255;
    int ww = (wx * 8 + px + SHIFT) & 255;
    return ((bi << 8 | hh) << 8 | ww) * C;
}

__device__ __forceinline__ uint32_t smem_u32(const void* p) {
    return (uint32_t)__cvta_generic_to_shared(p);
}
__device__ __forceinline__ void ldsm4(uint32_t& r0, uint32_t& r1, uint32_t& r2,
                                      uint32_t& r3, uint32_t a) {
    asm volatile("ldmatrix.sync.aligned.m8n8.x4.shared.b16 {%0,%1,%2,%3},[%4];\n"
                 : "=r"(r0), "=r"(r1), "=r"(r2), "=r"(r3) : "r"(a));
}
__device__ __forceinline__ void ldsm4t(uint32_t& r0, uint32_t& r1, uint32_t& r2,
                                       uint32_t& r3, uint32_t a) {
    asm volatile("ldmatrix.sync.aligned.m8n8.x4.trans.shared.b16 {%0,%1,%2,%3},[%4];\n"
                 : "=r"(r0), "=r"(r1), "=r"(r2), "=r"(r3) : "r"(a));
}
__device__ __forceinline__ void mma16816(float* c, const uint32_t* a, const uint32_t* b) {
    asm volatile(
        "mma.sync.aligned.m16n8k16.row.col.f32.f16.f16.f32 "
        "{%0,%1,%2,%3},{%4,%5,%6,%7},{%8,%9},{%0,%1,%2,%3};\n"
        : "+f"(c[0]), "+f"(c[1]), "+f"(c[2]), "+f"(c[3])
        : "r"(a[0]), "r"(a[1]), "r"(a[2]), "r"(a[3]), "r"(b[0]), "r"(b[1]));
}

// ---------------------------------------------------------------------------
// Kernel 0: convert weights fp32 -> fp16 once per launch.
// ---------------------------------------------------------------------------
__global__ __launch_bounds__(256) void prep_kernel(
    const float* __restrict__ w_qkv, const float* __restrict__ w_qkv_b,
    const float* __restrict__ w_out)
{
    int i = blockIdx.x * 256 + threadIdx.x;
    if (i < 576 * C) {
        gw_qkv [i] = __float2half_rn(w_qkv[i]);
        gw_qkvb[i] = __float2half_rn(w_qkv_b[i]);
    }
    if (i < C * C) gw_out[i] = __float2half_rn(w_out[i]);
}

// ---------------------------------------------------------------------------
// Kernel 1: QKV projection (fused roll+window gather), fp16 MMA.
// grid (9 n-tiles, 1024 m-tiles), 256 threads. CTA tile 128x64, K=192.
// ---------------------------------------------------------------------------
#define STRD 40   // padded smem row stride in halves (80B -> conflict-free LDSM)

__global__ __launch_bounds__(256) void qkv_mma_kernel(
    const float* __restrict__ x, const float* __restrict__ b,
    const float* __restrict__ b_qkv, const float* __restrict__ b_qkv_b)
{
    const int nt = blockIdx.x;           // 0..8
    const int mt = blockIdx.y;           // 0..1023
    const int region = nt / 3;           // 0=q, 1=k, 2=v
    const int n0 = nt * 64;
    const int m0 = mt * 128;

    const float*  src = (region == 0) ? b        : x;
    const __half* wgt = (region == 0) ? gw_qkvb  : gw_qkv;
    const float*  bia = (region == 0) ? b_qkv_b  : b_qkv;
    __half*       dst = (region == 0) ? g_q : (region == 1) ? g_k : g_v;
    const int coloff = region * 192;

    __shared__ __half As[128 * STRD];
    __shared__ __half Bs[64 * STRD];

    const int tid  = threadIdx.x;
    const int warp = tid >> 5, lane = tid & 31;
    const int wm = (warp >> 1) * 32, wn = (warp & 1) * 32;

    // loader A: 2 threads per row, 16 floats each -> fp16
    const int arow = tid >> 1, aoff = (tid & 1) * 16;
    const float* asrc = src + tok_to_pix_row(m0 + arow) + aoff;
    __half* adst = As + arow * STRD + aoff;
    // loader B: 4 threads per weight row, 8 halves each
    const int brow = tid >> 2, boff = (tid & 3) * 8;
    const __half* bsrc = wgt + (size_t)(n0 + brow) * C + boff;
    __half* bdst = Bs + brow * STRD + boff;

    float acc[2][4][4] = {};

    for (int k0 = 0; k0 < C; k0 += 32) {
        float4 f0 = *(const float4*)(asrc + k0 + 0);
        float4 f1 = *(const float4*)(asrc + k0 + 4);
        float4 f2 = *(const float4*)(asrc + k0 + 8);
        float4 f3 = *(const float4*)(asrc + k0 + 12);
        uint4  bw = *(const uint4*)(bsrc + k0);
        __half2 hh[8];
        hh[0] = __floats2half2_rn(f0.x, f0.y); hh[1] = __floats2half2_rn(f0.z, f0.w);
        hh[2] = __floats2half2_rn(f1.x, f1.y); hh[3] = __floats2half2_rn(f1.z, f1.w);
        hh[4] = __floats2half2_rn(f2.x, f2.y); hh[5] = __floats2half2_rn(f2.z, f2.w);
        hh[6] = __floats2half2_rn(f3.x, f3.y); hh[7] = __floats2half2_rn(f3.z, f3.w);
        __syncthreads();
        *(uint4*)adst       = *(uint4*)&hh[0];
        *(uint4*)(adst + 8) = *(uint4*)&hh[4];
        *(uint4*)bdst       = bw;
        __syncthreads();

        #pragma unroll
        for (int kk = 0; kk < 32; kk += 16) {
            uint32_t afr[2][4], bfr[4][2];
            #pragma unroll
            for (int mtile = 0; mtile < 2; ++mtile) {
                uint32_t aa = smem_u32(&As[(wm + 16 * mtile + (lane & 15)) * STRD
                                           + kk + 8 * (lane >> 4)]);
                ldsm4(afr[mtile][0], afr[mtile][1], afr[mtile][2], afr[mtile][3], aa);
            }
            #pragma unroll
            for (int g = 0; g < 2; ++g) {
                int m = lane >> 3;
                uint32_t ba = smem_u32(&Bs[(wn + 16 * g + (lane & 7) + 8 * (m >> 1)) * STRD
                                           + kk + 8 * (m & 1)]);
                ldsm4(bfr[2*g][0], bfr[2*g][1], bfr[2*g+1][0], bfr[2*g+1][1], ba);
            }
            #pragma unroll
            for (int mtile = 0; mtile < 2; ++mtile)
                #pragma unroll
                for (int ntile = 0; ntile < 4; ++ntile)
                    mma16816(acc[mtile][ntile], afr[mtile], bfr[ntile]);
        }
    }

    // epilogue: bias + store fp16 (half2 pairs)
    #pragma unroll
    for (int ntile = 0; ntile < 4; ++ntile) {
        int colg = n0 + wn + 8 * ntile + 2 * (lane & 3);
        float b0 = bia[colg], b1 = bia[colg + 1];
        int cl = colg - coloff;
        #pragma unroll
        for (int mtile = 0; mtile < 2; ++mtile) {
            int r0 = m0 + wm + 16 * mtile + (lane >> 2);
            *(__half2*)(dst + (size_t)r0 * C + cl) =
                __floats2half2_rn(acc[mtile][ntile][0] + b0, acc[mtile][ntile][1] + b1);
            *(__half2*)(dst + (size_t)(r0 + 8) * C + cl) =
                __floats2half2_rn(acc[mtile][ntile][2] + b0, acc[mtile][ntile][3] + b1);
        }
    }
}

// ---------------------------------------------------------------------------
// Kernel 2: per-(window,head) attention, fp16 MMA, P kept in registers.
// grid (2048, 6), 128 threads (4 warps, 16 query rows each).
// ---------------------------------------------------------------------------
__global__ __launch_bounds__(128) void attn_mma_kernel(const float* __restrict__ rel)
{
    const int wg   = blockIdx.x;
    const int head = blockIdx.y;
    const int win  = wg & 1023;
    const int wy   = win >> 5, wx = win & 31;
    const bool maskY = (wy == 31), maskX = (wx == 31);

    __shared__ __half Qs[64 * STRD];
    __shared__ __half Ks[64 * STRD];
    __shared__ __half Vs[64 * STRD];
    __shared__ float rel_s[225];

    const int tid = threadIdx.x, warp = tid >> 5, lane = tid & 31;
    const __half* qb = g_q + (size_t)wg * 64 * C + head * 32;
    const __half* kb = g_k + (size_t)wg * 64 * C + head * 32;
    const __half* vb = g_v + (size_t)wg * 64 * C + head * 32;

    #pragma unroll
    for (int i = tid; i < 256; i += 128) {
        int row = i >> 2, ch = (i & 3) * 8;
        *(uint4*)&Qs[row * STRD + ch] = *(const uint4*)(qb + (size_t)row * C + ch);
        *(uint4*)&Ks[row * STRD + ch] = *(const uint4*)(kb + (size_t)row * C + ch);
        *(uint4*)&Vs[row * STRD + ch] = *(const uint4*)(vb + (size_t)row * C + ch);
    }
    for (int i = tid; i < 225; i += 128) rel_s[i] = rel[head * 225 + i];
    __syncthreads();

    // ---- S = Q K^T (rows 16*warp..+15, all 64 cols) ----
    float c[8][4] = {};
    #pragma unroll
    for (int kk = 0; kk < 32; kk += 16) {
        uint32_t afr[4], bfr[8][2];
        uint32_t aa = smem_u32(&Qs[(16 * warp + (lane & 15)) * STRD + kk + 8 * (lane >> 4)]);
        ldsm4(afr[0], afr[1], afr[2], afr[3], aa);
        #pragma unroll
        for (int g = 0; g < 4; ++g) {
            int m = lane >> 3;
            uint32_t ba = smem_u32(&Ks[(16 * g + (lane & 7) + 8 * (m >> 1)) * STRD
                                       + kk + 8 * (m & 1)]);
            ldsm4(bfr[2*g][0], bfr[2*g][1], bfr[2*g+1][0], bfr[2*g+1][1], ba);
        }
        #pragma unroll
        for (int nt = 0; nt < 8; ++nt) mma16816(c[nt], afr, bfr[nt]);
    }

    // ---- scale + rel bias + shift mask (fragment registers) ----
    const int r1 = 16 * warp + (lane >> 2), r2 = r1 + 8;
    const int r1y = r1 >> 3, r1x = r1 & 7, r2y = r2 >> 3, r2x = r2 & 7;
    const int qx0 = 2 * (lane & 3), qx1 = qx0 + 1;
    #pragma unroll
    for (int nt = 0; nt < 8; ++nt) {
        bool m10 = (maskY && ((r1y < 4) != (nt < 4))) || (maskX && ((r1x < 4) != (qx0 < 4)));
        bool m11 = (maskY && ((r1y < 4) != (nt < 4))) || (maskX && ((r1x < 4) != (qx1 < 4)));
        bool m20 = (maskY && ((r2y < 4) != (nt < 4))) || (maskX && ((r2x < 4) != (qx0 < 4)));
        bool m21 = (maskY && ((r2y < 4) != (nt < 4))) || (maskX && ((r2x < 4) != (qx1 < 4)));
        float v0 = c[nt][0] * SCALE + rel_s[(r1y - nt + 7) * 15 + (r1x - qx0 + 7)];
        float v1 = c[nt][1] * SCALE + rel_s[(r1y - nt + 7) * 15 + (r1x - qx1 + 7)];
        float v2 = c[nt][2] * SCALE + rel_s[(r2y - nt + 7) * 15 + (r2x - qx0 + 7)];
        float v3 = c[nt][3] * SCALE + rel_s[(r2y - nt + 7) * 15 + (r2x - qx1 + 7)];
        c[nt][0] = m10 ? -1e30f : v0;
        c[nt][1] = m11 ? -1e30f : v1;
        c[nt][2] = m20 ? -1e30f : v2;
        c[nt][3] = m21 ? -1e30f : v3;
    }

    // ---- softmax per row (quad = lanes sharing t>>2) ----
    float mx1 = -1e30f, mx2 = -1e30f;
    #pragma unroll
    for (int nt = 0; nt < 8; ++nt) {
        mx1 = fmaxf(mx1, fmaxf(c[nt][0], c[nt][1]));
        mx2 = fmaxf(mx2, fmaxf(c[nt][2], c[nt][3]));
    }
    mx1 = fmaxf(mx1, __shfl_xor_sync(0xffffffffu, mx1, 1));
    mx1 = fmaxf(mx1, __shfl_xor_sync(0xffffffffu, mx1, 2));
    mx2 = fmaxf(mx2, __shfl_xor_sync(0xffffffffu, mx2, 1));
    mx2 = fmaxf(mx2, __shfl_xor_sync(0xffffffffu, mx2, 2));
    float s1 = 0.f, s2 = 0.f;
    #pragma unroll
    for (int nt = 0; nt < 8; ++nt) {
        c[nt][0] = __expf(c[nt][0] - mx1); s1 += c[nt][0];
        c[nt][1] = __expf(c[nt][1] - mx1); s1 += c[nt][1];
        c[nt][2] = __expf(c[nt][2] - mx2); s2 += c[nt][2];
        c[nt][3] = __expf(c[nt][3] - mx2); s2 += c[nt][3];
    }
    s1 += __shfl_xor_sync(0xffffffffu, s1, 1);
    s1 += __shfl_xor_sync(0xffffffffu, s1, 2);
    s2 += __shfl_xor_sync(0xffffffffu, s2, 1);
    s2 += __shfl_xor_sync(0xffffffffu, s2, 2);
    const float i1 = 1.f / s1, i2 = 1.f / s2;

    // ---- P -> fp16 A-fragments (no smem round-trip) ----
    uint32_t p[4][4];
    #pragma unroll
    for (int kt = 0; kt < 4; ++kt) {
        __half2 h0 = __floats2half2_rn(c[2*kt  ][0] * i1, c[2*kt  ][1] * i1);
        __half2 h1 = __floats2half2_rn(c[2*kt  ][2] * i2, c[2*kt  ][3] * i2);
        __half2 h2 = __floats2half2_rn(c[2*kt+1][0] * i1, c[2*kt+1][1] * i1);
        __half2 h3 = __floats2half2_rn(c[2*kt+1][2] * i2, c[2*kt+1][3] * i2);
        p[kt][0] = *(uint32_t*)&h0; p[kt][1] = *(uint32_t*)&h1;
        p[kt][2] = *(uint32_t*)&h2; p[kt][3] = *(uint32_t*)&h3;
    }

    // ---- O = P V (V via ldmatrix.trans) ----
    float o[4][4] = {};
    #pragma unroll
    for (int kt = 0; kt < 4; ++kt) {
        uint32_t vfr[4][2];
        #pragma unroll
        for (int g = 0; g < 2; ++g) {
            int m = lane >> 3;
            uint32_t va = smem_u32(&Vs[(16 * kt + (lane & 7) + 8 * (m & 1)) * STRD
                                       + 16 * g + 8 * (m >> 1)]);
            ldsm4t(vfr[2*g][0], vfr[2*g][1], vfr[2*g+1][0], vfr[2*g+1][1], va);
        }
        #pragma unroll
        for (int nt = 0; nt < 4; ++nt) mma16816(o[nt], p[kt], vfr[nt]);
    }

    // ---- store O fp16 ----
    __half* ob = g_ao + (size_t)wg * 64 * C + head * 32;
    #pragma unroll
    for (int nt = 0; nt < 4; ++nt) {
        int colp = 8 * nt + 2 * (lane & 3);
        *(__half2*)(ob + (size_t)r1 * C + colp) = __floats2half2_rn(o[nt][0], o[nt][1]);
        *(__half2*)(ob + (size_t)r2 * C + colp) = __floats2half2_rn(o[nt][2], o[nt][3]);
    }
}

// ---------------------------------------------------------------------------
// Kernel 3: output projection + bias, fused window departition + roll scatter.
// grid (3, 1024), 256 threads. CTA tile 128x64, K=192, fp32 output.
// ---------------------------------------------------------------------------
__global__ __launch_bounds__(256) void proj_mma_kernel(
    const float* __restrict__ b_out, float* __restrict__ out)
{
    const int nt = blockIdx.x;           // 0..2
    const int mt = blockIdx.y;
    const int n0 = nt * 64;
    const int m0 = mt * 128;

    __shared__ __half As[128 * STRD];
    __shared__ __half Bs[64 * STRD];

    const int tid  = threadIdx.x;
    const int warp = tid >> 5, lane = tid & 31;
    const int wm = (warp >> 1) * 32, wn = (warp & 1) * 32;

    const int arow = tid >> 1, aoff = (tid & 1) * 16;
    const __half* asrc = g_ao + (size_t)(m0 + arow) * C + aoff;
    __half* adst = As + arow * STRD + aoff;
    const int brow = tid >> 2, boff = (tid & 3) * 8;
    const __half* bsrc = gw_out + (size_t)(n0 + brow) * C + boff;
    __half* bdst = Bs + brow * STRD + boff;

    float acc[2][4][4] = {};

    for (int k0 = 0; k0 < C; k0 += 32) {
        uint4 a0 = *(const uint4*)(asrc + k0);
        uint4 a1 = *(const uint4*)(asrc + k0 + 8);
        uint4 bw = *(const uint4*)(bsrc + k0);
        __syncthreads();
        *(uint4*)adst       = a0;
        *(uint4*)(adst + 8) = a1;
        *(uint4*)bdst       = bw;
        __syncthreads();

        #pragma unroll
        for (int kk = 0; kk < 32; kk += 16) {
            uint32_t afr[2][4], bfr[4][2];
            #pragma unroll
            for (int mtile = 0; mtile < 2; ++mtile) {
                uint32_t aa = smem_u32(&As[(wm + 16 * mtile + (lane & 15)) * STRD
                                           + kk + 8 * (lane >> 4)]);
                ldsm4(afr[mtile][0], afr[mtile][1], afr[mtile][2], afr[mtile][3], aa);
            }
            #pragma unroll
            for (int g = 0; g < 2; ++g) {
                int m = lane >> 3;
                uint32_t ba = smem_u32(&Bs[(wn + 16 * g + (lane & 7) + 8 * (m >> 1)) * STRD
                                           + kk + 8 * (m & 1)]);
                ldsm4(bfr[2*g][0], bfr[2*g][1], bfr[2*g+1][0], bfr[2*g+1][1], ba);
            }
            #pragma unroll
            for (int mtile = 0; mtile < 2; ++mtile)
                #pragma unroll
                for (int ntile = 0; ntile < 4; ++ntile)
                    mma16816(acc[mtile][ntile], afr[mtile], bfr[ntile]);
        }
    }

    // epilogue: bias + scatter fp32 to output image
    #pragma unroll
    for (int ntile = 0; ntile < 4; ++ntile) {
        int colg = n0 + wn + 8 * ntile + 2 * (lane & 3);
        float b0 = b_out[colg], b1 = b_out[colg + 1];
        #pragma unroll
        for (int mtile = 0; mtile < 2; ++mtile) {
            int tok = m0 + wm + 16 * mtile + (lane >> 2);
            float* d0 = out + tok_to_pix_row(tok) + colg;
            float* d1 = out + tok_to_pix_row(tok + 8) + colg;
            *(float2*)d0 = make_float2(acc[mtile][ntile][0] + b0,
                                       acc[mtile][ntile][1] + b1);
            *(float2*)d1 = make_float2(acc[mtile][ntile][2] + b0,
                                       acc[mtile][ntile][3] + b1);
        }
    }
}

// ---------------------------------------------------------------------------
extern "C" void kernel_launch(void* const* d_in, const int* in_sizes, int n_in,
                              void* d_out, int out_size)
{
    const float* x        = (const float*)d_in[0];
    const float* b        = (const float*)d_in[1];
    const float* w_qkv    = (const float*)d_in[2];
    const float* b_qkv    = (const float*)d_in[3];
    const float* w_qkv_b  = (const float*)d_in[4];
    const float* b_qkv_b  = (const float*)d_in[5];
    const float* rel      = (const float*)d_in[6];
    const float* w_out    = (const float*)d_in[7];
    const float* b_out    = (const float*)d_in[8];
    float* out = (float*)d_out;

    prep_kernel<<<432, 256>>>(w_qkv, w_qkv_b, w_out);
    qkv_mma_kernel<<<dim3(9, 1024), 256>>>(x, b, b_qkv, b_qkv_b);
    attn_mma_kernel<<<dim3(2048, 6), 128>>>(rel);
    proj_mma_kernel<<<dim3(3, 1024), 256>>>(b_out, out);
}

// round 4
// speedup vs baseline: 4.7826x; 1.3839x over previous
#include <cuda_runtime.h>
#include <cuda_fp16.h>
#include <cstdint>

// ---------------------------------------------------------------------------
// Swin shifted-window attention, R4: mma.sync HMMA, A-resident GEMM structure.
// (tcgen05 unavailable: harness PTX targets sm_103 without the 'a' feature set)
// ---------------------------------------------------------------------------

#define C       192
#define SHIFT   4
#define NTOK    (2*1024*64)
#define SCALE   0.17677669529663687f
#define ASTR    200              // smem row stride in halves (400B, LDSM conflict-free)

__device__ __half g_q  [NTOK * C];
__device__ __half g_k  [NTOK * C];
__device__ __half g_v  [NTOK * C];
__device__ __half g_ao [NTOK * C];
__device__ __half gw_qkv [576 * C];
__device__ __half gw_qkvb[576 * C];
__device__ __half gw_out [C * C];

__device__ __forceinline__ int tok_to_pix_row(int tok) {
    int bi  = tok >> 16;
    int rr  = tok & 65535;
    int win = rr >> 6, pix = rr & 63;
    int wy = win >> 5, wx = win & 31;
    int py = pix >> 3, px = pix & 7;
    int hh = (wy * 8 + py + SHIFT) & 255;
    int ww = (wx * 8 + px + SHIFT) & 255;
    return ((bi << 8 | hh) << 8 | ww) * C;
}

__device__ __forceinline__ uint32_t smem_u32(const void* p) {
    return (uint32_t)__cvta_generic_to_shared(p);
}
__device__ __forceinline__ void ldsm4(uint32_t& r0, uint32_t& r1, uint32_t& r2,
                                      uint32_t& r3, uint32_t a) {
    asm volatile("ldmatrix.sync.aligned.m8n8.x4.shared.b16 {%0,%1,%2,%3},[%4];\n"
                 : "=r"(r0), "=r"(r1), "=r"(r2), "=r"(r3) : "r"(a));
}
__device__ __forceinline__ void ldsm4t(uint32_t& r0, uint32_t& r1, uint32_t& r2,
                                       uint32_t& r3, uint32_t a) {
    asm volatile("ldmatrix.sync.aligned.m8n8.x4.trans.shared.b16 {%0,%1,%2,%3},[%4];\n"
                 : "=r"(r0), "=r"(r1), "=r"(r2), "=r"(r3) : "r"(a));
}
__device__ __forceinline__ void mma16816(float* c, const uint32_t* a, const uint32_t* b) {
    asm volatile(
        "mma.sync.aligned.m16n8k16.row.col.f32.f16.f16.f32 "
        "{%0,%1,%2,%3},{%4,%5,%6,%7},{%8,%9},{%0,%1,%2,%3};\n"
        : "+f"(c[0]), "+f"(c[1]), "+f"(c[2]), "+f"(c[3])
        : "r"(a[0]), "r"(a[1]), "r"(a[2]), "r"(a[3]), "r"(b[0]), "r"(b[1]));
}

// ---------------------------------------------------------------------------
// Kernel 0: weight conversion fp32 -> fp16
// ---------------------------------------------------------------------------
__global__ __launch_bounds__(256) void prep_kernel(
    const float* __restrict__ w_qkv, const float* __restrict__ w_qkv_b,
    const float* __restrict__ w_out)
{
    int i = blockIdx.x * 256 + threadIdx.x;
    if (i < 576 * C) {
        gw_qkv [i] = __float2half_rn(w_qkv[i]);
        gw_qkvb[i] = __float2half_rn(w_qkv_b[i]);
    }
    if (i < C * C) gw_out[i] = __float2half_rn(w_out[i]);
}

// ---------------------------------------------------------------------------
// Kernel 1: QKV projection. grid(1024), 256 threads. A tile (128x192 fp16)
// resident in smem, loaded ONCE per source (b for q; x for k,v). 6 N-groups
// of 96 weight cols. Warp tile 32x48 (8 warps: 4m x 2n).
// ---------------------------------------------------------------------------
__global__ __launch_bounds__(256)
void qkv_kernel(const float* __restrict__ xin, const float* __restrict__ bin,
                const float* __restrict__ b_qkv, const float* __restrict__ b_qkv_b)
{
    extern __shared__ __half sm[];
    __half* As = sm;                 // 128 * ASTR
    __half* Bs = sm + 128 * ASTR;    // 96 * ASTR

    const int tid = threadIdx.x, warp = tid >> 5, lane = tid & 31;
    const int m0 = blockIdx.x * 128;
    const int wm = (warp >> 1) * 32;      // warp m base (4 quadrants)
    const int wn = (warp & 1) * 48;       // warp n base (2 quadrants)

    // precompute A gather source rows (12 uint4-tasks per thread)
    int apix[6];
    #pragma unroll
    for (int t = 0; t < 6; ++t) {
        int i = tid + t * 512;            // tasks 0..3071, 2 per entry below
        apix[t] = tok_to_pix_row(m0 + (i / 24));
    }

    for (int gg = 0; gg < 6; ++gg) {
        __syncthreads();   // prior group's LDSM done before overwriting smem

        // ---- A load + convert (only when source changes) ----
        if (gg == 0 || gg == 2) {
            const float* src = (gg == 0) ? bin : xin;
            #pragma unroll
            for (int t = 0; t < 6; ++t) {
                int i = tid + t * 512;    // two 8-half tasks per iteration
                #pragma unroll
                for (int h = 0; h < 2; ++h) {
                    int ii = i + h * 256;
                    int row = ii / 24, off = (ii % 24) * 8;
                    const float* p = src + tok_to_pix_row(m0 + row) + off;
                    float4 f0 = *(const float4*)p;
                    float4 f1 = *(const float4*)(p + 4);
                    __half2 hh[4] = { __floats2half2_rn(f0.x, f0.y),
                                      __floats2half2_rn(f0.z, f0.w),
                                      __floats2half2_rn(f1.x, f1.y),
                                      __floats2half2_rn(f1.z, f1.w) };
                    *(uint4*)&As[row * ASTR + off] = *(uint4*)hh;
                }
            }
        }
        // ---- B load: 96 weight rows x 192 halves ----
        {
            const __half* wbase = ((gg < 2) ? gw_qkvb : gw_qkv) + (size_t)gg * 96 * C;
            #pragma unroll
            for (int t = 0; t < 9; ++t) {
                int i = tid + t * 256;    // 2304 tasks of 8 halves
                int row = i / 24, off = (i % 24) * 8;
                *(uint4*)&Bs[row * ASTR + off] = *(const uint4*)(wbase + row * C + off);
            }
        }
        __syncthreads();

        // ---- mainloop: K = 192, 12 steps of 16 ----
        float acc[2][6][4] = {};
        #pragma unroll
        for (int kk = 0; kk < 192; kk += 16) {
            uint32_t afr[2][4], bfr[6][2];
            #pragma unroll
            for (int mt = 0; mt < 2; ++mt) {
                uint32_t aa = smem_u32(&As[(wm + 16 * mt + (lane & 15)) * ASTR
                                           + kk + 8 * (lane >> 4)]);
                ldsm4(afr[mt][0], afr[mt][1], afr[mt][2], afr[mt][3], aa);
            }
            #pragma unroll
            for (int g = 0; g < 3; ++g) {
                int m = lane >> 3;
                uint32_t ba = smem_u32(&Bs[(wn + 16 * g + (lane & 7) + 8 * (m >> 1)) * ASTR
                                           + kk + 8 * (m & 1)]);
                ldsm4(bfr[2*g][0], bfr[2*g][1], bfr[2*g+1][0], bfr[2*g+1][1], ba);
            }
            #pragma unroll
            for (int mt = 0; mt < 2; ++mt)
                #pragma unroll
                for (int nt = 0; nt < 6; ++nt)
                    mma16816(acc[mt][nt], afr[mt], bfr[nt]);
        }

        // ---- epilogue: bias + fp16 store ----
        const int region = gg >> 1;
        __half* dst = (region == 0) ? g_q : (region == 1) ? g_k : g_v;
        const float* bia = (gg < 2) ? b_qkv_b : b_qkv;
        #pragma unroll
        for (int nt = 0; nt < 6; ++nt) {
            int colg = gg * 96 + wn + 8 * nt + 2 * (lane & 3);
            float b0 = bia[colg], b1 = bia[colg + 1];
            int cl = colg - region * 192;
            #pragma unroll
            for (int mt = 0; mt < 2; ++mt) {
                int r0 = m0 + wm + 16 * mt + (lane >> 2);
                *(__half2*)(dst + (size_t)r0 * C + cl) =
                    __floats2half2_rn(acc[mt][nt][0] + b0, acc[mt][nt][1] + b1);
                *(__half2*)(dst + (size_t)(r0 + 8) * C + cl) =
                    __floats2half2_rn(acc[mt][nt][2] + b0, acc[mt][nt][3] + b1);
            }
        }
    }
}

// ---------------------------------------------------------------------------
// Kernel 3: output projection. grid(1024), 256 threads. A = g_ao (fp16)
// resident, loaded once. 2 N-groups of 96. fp32 scatter w/ roll-back.
// ---------------------------------------------------------------------------
__global__ __launch_bounds__(256)
void proj_kernel(const float* __restrict__ b_out, float* __restrict__ out)
{
    extern __shared__ __half sm[];
    __half* As = sm;
    __half* Bs = sm + 128 * ASTR;

    const int tid = threadIdx.x, warp = tid >> 5, lane = tid & 31;
    const int m0 = blockIdx.x * 128;
    const int wm = (warp >> 1) * 32;
    const int wn = (warp & 1) * 48;

    // A load (fp16 copy, once)
    #pragma unroll
    for (int t = 0; t < 12; ++t) {
        int i = tid + t * 256;            // 3072 tasks of 8 halves
        int row = i / 24, off = (i % 24) * 8;
        *(uint4*)&As[row * ASTR + off] =
            *(const uint4*)(g_ao + (size_t)(m0 + row) * C + off);
    }

    // precompute output scatter rows for this thread's 4 result rows
    int orow[2][2];
    #pragma unroll
    for (int mt = 0; mt < 2; ++mt) {
        int r0 = m0 + wm + 16 * mt + (lane >> 2);
        orow[mt][0] = tok_to_pix_row(r0);
        orow[mt][1] = tok_to_pix_row(r0 + 8);
    }

    for (int gg = 0; gg < 2; ++gg) {
        __syncthreads();
        {
            const __half* wbase = gw_out + (size_t)gg * 96 * C;
            #pragma unroll
            for (int t = 0; t < 9; ++t) {
                int i = tid + t * 256;
                int row = i / 24, off = (i % 24) * 8;
                *(uint4*)&Bs[row * ASTR + off] = *(const uint4*)(wbase + row * C + off);
            }
        }
        __syncthreads();

        float acc[2][6][4] = {};
        #pragma unroll
        for (int kk = 0; kk < 192; kk += 16) {
            uint32_t afr[2][4], bfr[6][2];
            #pragma unroll
            for (int mt = 0; mt < 2; ++mt) {
                uint32_t aa = smem_u32(&As[(wm + 16 * mt + (lane & 15)) * ASTR
                                           + kk + 8 * (lane >> 4)]);
                ldsm4(afr[mt][0], afr[mt][1], afr[mt][2], afr[mt][3], aa);
            }
            #pragma unroll
            for (int g = 0; g < 3; ++g) {
                int m = lane >> 3;
                uint32_t ba = smem_u32(&Bs[(wn + 16 * g + (lane & 7) + 8 * (m >> 1)) * ASTR
                                           + kk + 8 * (m & 1)]);
                ldsm4(bfr[2*g][0], bfr[2*g][1], bfr[2*g+1][0], bfr[2*g+1][1], ba);
            }
            #pragma unroll
            for (int mt = 0; mt < 2; ++mt)
                #pragma unroll
                for (int nt = 0; nt < 6; ++nt)
                    mma16816(acc[mt][nt], afr[mt], bfr[nt]);
        }

        #pragma unroll
        for (int nt = 0; nt < 6; ++nt) {
            int colg = gg * 96 + wn + 8 * nt + 2 * (lane & 3);
            float b0 = b_out[colg], b1 = b_out[colg + 1];
            #pragma unroll
            for (int mt = 0; mt < 2; ++mt) {
                *(float2*)(out + orow[mt][0] + colg) =
                    make_float2(acc[mt][nt][0] + b0, acc[mt][nt][1] + b1);
                *(float2*)(out + orow[mt][1] + colg) =
                    make_float2(acc[mt][nt][2] + b0, acc[mt][nt][3] + b1);
            }
        }
    }
}

// ---------------------------------------------------------------------------
// Kernel 2: attention (mma.sync), unchanged from R2.
// ---------------------------------------------------------------------------
#define STRD 40
__global__ __launch_bounds__(128) void attn_mma_kernel(const float* __restrict__ rel)
{
    const int wg   = blockIdx.x;
    const int head = blockIdx.y;
    const int win  = wg & 1023;
    const int wy   = win >> 5, wx = win & 31;
    const bool maskY = (wy == 31), maskX = (wx == 31);

    __shared__ __half Qs[64 * STRD];
    __shared__ __half Ks[64 * STRD];
    __shared__ __half Vs[64 * STRD];
    __shared__ float rel_s[225];

    const int tid = threadIdx.x, warp = tid >> 5, lane = tid & 31;
    const __half* qb = g_q + (size_t)wg * 64 * C + head * 32;
    const __half* kb = g_k + (size_t)wg * 64 * C + head * 32;
    const __half* vb = g_v + (size_t)wg * 64 * C + head * 32;

    #pragma unroll
    for (int i = tid; i < 256; i += 128) {
        int row = i >> 2, ch = (i & 3) * 8;
        *(uint4*)&Qs[row * STRD + ch] = *(const uint4*)(qb + (size_t)row * C + ch);
        *(uint4*)&Ks[row * STRD + ch] = *(const uint4*)(kb + (size_t)row * C + ch);
        *(uint4*)&Vs[row * STRD + ch] = *(const uint4*)(vb + (size_t)row * C + ch);
    }
    for (int i = tid; i < 225; i += 128) rel_s[i] = rel[head * 225 + i];
    __syncthreads();

    float c[8][4] = {};
    #pragma unroll
    for (int kk = 0; kk < 32; kk += 16) {
        uint32_t afr[4], bfr[8][2];
        uint32_t aa = smem_u32(&Qs[(16 * warp + (lane & 15)) * STRD + kk + 8 * (lane >> 4)]);
        ldsm4(afr[0], afr[1], afr[2], afr[3], aa);
        #pragma unroll
        for (int g = 0; g < 4; ++g) {
            int m = lane >> 3;
            uint32_t ba = smem_u32(&Ks[(16 * g + (lane & 7) + 8 * (m >> 1)) * STRD
                                       + kk + 8 * (m & 1)]);
            ldsm4(bfr[2*g][0], bfr[2*g][1], bfr[2*g+1][0], bfr[2*g+1][1], ba);
        }
        #pragma unroll
        for (int nt = 0; nt < 8; ++nt) mma16816(c[nt], afr, bfr[nt]);
    }

    const int r1 = 16 * warp + (lane >> 2), r2 = r1 + 8;
    const int r1y = r1 >> 3, r1x = r1 & 7, r2y = r2 >> 3, r2x = r2 & 7;
    const int qx0 = 2 * (lane & 3), qx1 = qx0 + 1;
    #pragma unroll
    for (int nt = 0; nt < 8; ++nt) {
        bool m10 = (maskY && ((r1y < 4) != (nt < 4))) || (maskX && ((r1x < 4) != (qx0 < 4)));
        bool m11 = (maskY && ((r1y < 4) != (nt < 4))) || (maskX && ((r1x < 4) != (qx1 < 4)));
        bool m20 = (maskY && ((r2y < 4) != (nt < 4))) || (maskX && ((r2x < 4) != (qx0 < 4)));
        bool m21 = (maskY && ((r2y < 4) != (nt < 4))) || (maskX && ((r2x < 4) != (qx1 < 4)));
        float v0 = c[nt][0] * SCALE + rel_s[(r1y - nt + 7) * 15 + (r1x - qx0 + 7)];
        float v1 = c[nt][1] * SCALE + rel_s[(r1y - nt + 7) * 15 + (r1x - qx1 + 7)];
        float v2 = c[nt][2] * SCALE + rel_s[(r2y - nt + 7) * 15 + (r2x - qx0 + 7)];
        float v3 = c[nt][3] * SCALE + rel_s[(r2y - nt + 7) * 15 + (r2x - qx1 + 7)];
        c[nt][0] = m10 ? -1e30f : v0;
        c[nt][1] = m11 ? -1e30f : v1;
        c[nt][2] = m20 ? -1e30f : v2;
        c[nt][3] = m21 ? -1e30f : v3;
    }

    float mx1 = -1e30f, mx2 = -1e30f;
    #pragma unroll
    for (int nt = 0; nt < 8; ++nt) {
        mx1 = fmaxf(mx1, fmaxf(c[nt][0], c[nt][1]));
        mx2 = fmaxf(mx2, fmaxf(c[nt][2], c[nt][3]));
    }
    mx1 = fmaxf(mx1, __shfl_xor_sync(0xffffffffu, mx1, 1));
    mx1 = fmaxf(mx1, __shfl_xor_sync(0xffffffffu, mx1, 2));
    mx2 = fmaxf(mx2, __shfl_xor_sync(0xffffffffu, mx2, 1));
    mx2 = fmaxf(mx2, __shfl_xor_sync(0xffffffffu, mx2, 2));
    float s1 = 0.f, s2 = 0.f;
    #pragma unroll
    for (int nt = 0; nt < 8; ++nt) {
        c[nt][0] = __expf(c[nt][0] - mx1); s1 += c[nt][0];
        c[nt][1] = __expf(c[nt][1] - mx1); s1 += c[nt][1];
        c[nt][2] = __expf(c[nt][2] - mx2); s2 += c[nt][2];
        c[nt][3] = __expf(c[nt][3] - mx2); s2 += c[nt][3];
    }
    s1 += __shfl_xor_sync(0xffffffffu, s1, 1);
    s1 += __shfl_xor_sync(0xffffffffu, s1, 2);
    s2 += __shfl_xor_sync(0xffffffffu, s2, 1);
    s2 += __shfl_xor_sync(0xffffffffu, s2, 2);
    const float i1 = 1.f / s1, i2 = 1.f / s2;

    uint32_t p[4][4];
    #pragma unroll
    for (int kt = 0; kt < 4; ++kt) {
        __half2 h0 = __floats2half2_rn(c[2*kt  ][0] * i1, c[2*kt  ][1] * i1);
        __half2 h1 = __floats2half2_rn(c[2*kt  ][2] * i2, c[2*kt  ][3] * i2);
        __half2 h2 = __floats2half2_rn(c[2*kt+1][0] * i1, c[2*kt+1][1] * i1);
        __half2 h3 = __floats2half2_rn(c[2*kt+1][2] * i2, c[2*kt+1][3] * i2);
        p[kt][0] = *(uint32_t*)&h0; p[kt][1] = *(uint32_t*)&h1;
        p[kt][2] = *(uint32_t*)&h2; p[kt][3] = *(uint32_t*)&h3;
    }

    float o[4][4] = {};
    #pragma unroll
    for (int kt = 0; kt < 4; ++kt) {
        uint32_t vfr[4][2];
        #pragma unroll
        for (int g = 0; g < 2; ++g) {
            int m = lane >> 3;
            uint32_t va = smem_u32(&Vs[(16 * kt + (lane & 7) + 8 * (m & 1)) * STRD
                                       + 16 * g + 8 * (m >> 1)]);
            ldsm4t(vfr[2*g][0], vfr[2*g][1], vfr[2*g+1][0], vfr[2*g+1][1], va);
        }
        #pragma unroll
        for (int nt = 0; nt < 4; ++nt) mma16816(o[nt], p[kt], vfr[nt]);
    }

    __half* ob = g_ao + (size_t)wg * 64 * C + head * 32;
    #pragma unroll
    for (int nt = 0; nt < 4; ++nt) {
        int colp = 8 * nt + 2 * (lane & 3);
        *(__half2*)(ob + (size_t)r1 * C + colp) = __floats2half2_rn(o[nt][0], o[nt][1]);
        *(__half2*)(ob + (size_t)r2 * C + colp) = __floats2half2_rn(o[nt][2], o[nt][3]);
    }
}

// ---------------------------------------------------------------------------
#define GEMM_SMEM ((128 + 96) * ASTR * 2)   // 89600 bytes

extern "C" void kernel_launch(void* const* d_in, const int* in_sizes, int n_in,
                              void* d_out, int out_size)
{
    const float* x        = (const float*)d_in[0];
    const float* b        = (const float*)d_in[1];
    const float* w_qkv    = (const float*)d_in[2];
    const float* b_qkv    = (const float*)d_in[3];
    const float* w_qkv_b  = (const float*)d_in[4];
    const float* b_qkv_b  = (const float*)d_in[5];
    const float* rel      = (const float*)d_in[6];
    const float* w_out    = (const float*)d_in[7];
    const float* b_out    = (const float*)d_in[8];
    float* out = (float*)d_out;

    cudaFuncSetAttribute(qkv_kernel,  cudaFuncAttributeMaxDynamicSharedMemorySize, GEMM_SMEM);
    cudaFuncSetAttribute(proj_kernel, cudaFuncAttributeMaxDynamicSharedMemorySize, GEMM_SMEM);

    prep_kernel<<<432, 256>>>(w_qkv, w_qkv_b, w_out);
    qkv_kernel<<<1024, 256, GEMM_SMEM>>>(x, b, b_qkv, b_qkv_b);
    attn_mma_kernel<<<dim3(2048, 6), 128>>>(rel);
    proj_kernel<<<1024, 256, GEMM_SMEM>>>(b_out, out);
}

// round 5
// speedup vs baseline: 6.0522x; 1.2654x over previous
#include <cuda_runtime.h>
#include <cuda_fp16.h>
#include <cstdint>

// ---------------------------------------------------------------------------
// Swin shifted-window attention, R5: single fused megakernel.
// CTA = 128 tokens = 2 windows. q/k/v/O live entirely in shared memory.
// ---------------------------------------------------------------------------

#define C       192
#define SHIFT   4
#define NTOK    (2*1024*64)
#define SCALE   0.17677669529663687f
#define ASTR    200   // smem row stride in halves (400B, LDSM conflict-free)

__device__ __half gw_qkv [576 * C];
__device__ __half gw_qkvb[576 * C];
__device__ __half gw_out [C * C];

__device__ __forceinline__ int tok_to_pix_row(int tok) {
    int bi  = tok >> 16;
    int rr  = tok & 65535;
    int win = rr >> 6, pix = rr & 63;
    int wy = win >> 5, wx = win & 31;
    int py = pix >> 3, px = pix & 7;
    int hh = (wy * 8 + py + SHIFT) & 255;
    int ww = (wx * 8 + px + SHIFT) & 255;
    return ((bi << 8 | hh) << 8 | ww) * C;
}

__device__ __forceinline__ uint32_t smem_u32(const void* p) {
    return (uint32_t)__cvta_generic_to_shared(p);
}
__device__ __forceinline__ void ldsm4(uint32_t& r0, uint32_t& r1, uint32_t& r2,
                                      uint32_t& r3, uint32_t a) {
    asm volatile("ldmatrix.sync.aligned.m8n8.x4.shared.b16 {%0,%1,%2,%3},[%4];\n"
                 : "=r"(r0), "=r"(r1), "=r"(r2), "=r"(r3) : "r"(a));
}
__device__ __forceinline__ void ldsm4t(uint32_t& r0, uint32_t& r1, uint32_t& r2,
                                       uint32_t& r3, uint32_t a) {
    asm volatile("ldmatrix.sync.aligned.m8n8.x4.trans.shared.b16 {%0,%1,%2,%3},[%4];\n"
                 : "=r"(r0), "=r"(r1), "=r"(r2), "=r"(r3) : "r"(a));
}
__device__ __forceinline__ void mma16816(float* c, const uint32_t* a, const uint32_t* b) {
    asm volatile(
        "mma.sync.aligned.m16n8k16.row.col.f32.f16.f16.f32 "
        "{%0,%1,%2,%3},{%4,%5,%6,%7},{%8,%9},{%0,%1,%2,%3};\n"
        : "+f"(c[0]), "+f"(c[1]), "+f"(c[2]), "+f"(c[3])
        : "r"(a[0]), "r"(a[1]), "r"(a[2]), "r"(a[3]), "r"(b[0]), "r"(b[1]));
}

// ---------------------------------------------------------------------------
__global__ __launch_bounds__(256) void prep_kernel(
    const float* __restrict__ w_qkv, const float* __restrict__ w_qkv_b,
    const float* __restrict__ w_out)
{
    int i = blockIdx.x * 256 + threadIdx.x;
    if (i < 576 * C) {
        gw_qkv [i] = __float2half_rn(w_qkv[i]);
        gw_qkvb[i] = __float2half_rn(w_qkv_b[i]);
    }
    if (i < C * C) gw_out[i] = __float2half_rn(w_out[i]);
}

// ---------------------------------------------------------------------------
// fused helpers
// ---------------------------------------------------------------------------
__device__ __forceinline__ void stage_input(const float* __restrict__ src,
                                            __half* dst, int m0, int tid)
{
    #pragma unroll
    for (int t = 0; t < 12; ++t) {
        int i = tid + t * 256;          // 3072 tasks of 8 floats
        int row = i / 24, off = (i % 24) * 8;
        const float* p = src + tok_to_pix_row(m0 + row) + off;
        float4 f0 = *(const float4*)p;
        float4 f1 = *(const float4*)(p + 4);
        __half2 hh[4] = { __floats2half2_rn(f0.x, f0.y), __floats2half2_rn(f0.z, f0.w),
                          __floats2half2_rn(f1.x, f1.y), __floats2half2_rn(f1.z, f1.w) };
        *(uint4*)&dst[row * ASTR + off] = *(uint4*)hh;
    }
}

__device__ __forceinline__ void load_w(__half* dst, const __half* __restrict__ w, int tid)
{
    #pragma unroll
    for (int t = 0; t < 9; ++t) {
        int i = tid + t * 256;          // 2304 tasks of 8 halves (96 rows x 192)
        int row = i / 24, off = (i % 24) * 8;
        *(uint4*)&dst[row * ASTR + off] = *(const uint4*)(w + (size_t)row * C + off);
    }
}

// 128x96 GEMM over K=192: warp tile 32x48 (8 warps = 4m x 2n)
__device__ __forceinline__ void gemm_group(const __half* As, const __half* Bs,
                                           int lane, int wm, int wn, float acc[2][6][4])
{
    #pragma unroll
    for (int kk = 0; kk < 192; kk += 16) {
        uint32_t afr[2][4], bfr[6][2];
        #pragma unroll
        for (int mt = 0; mt < 2; ++mt) {
            uint32_t aa = smem_u32(&As[(wm + 16 * mt + (lane & 15)) * ASTR
                                       + kk + 8 * (lane >> 4)]);
            ldsm4(afr[mt][0], afr[mt][1], afr[mt][2], afr[mt][3], aa);
        }
        #pragma unroll
        for (int g = 0; g < 3; ++g) {
            int m = lane >> 3;
            uint32_t ba = smem_u32(&Bs[(wn + 16 * g + (lane & 7) + 8 * (m >> 1)) * ASTR
                                       + kk + 8 * (m & 1)]);
            ldsm4(bfr[2*g][0], bfr[2*g][1], bfr[2*g+1][0], bfr[2*g+1][1], ba);
        }
        #pragma unroll
        for (int mt = 0; mt < 2; ++mt)
            #pragma unroll
            for (int nt = 0; nt < 6; ++nt)
                mma16816(acc[mt][nt], afr[mt], bfr[nt]);
    }
}

// epilogue -> smem (fp16 + bias). bias pre-offset so bias[col], col in [0,96)
__device__ __forceinline__ void epi_smem(__half* dst, int colbase,
                                         const float* __restrict__ bias,
                                         int lane, int wm, int wn, float acc[2][6][4])
{
    #pragma unroll
    for (int nt = 0; nt < 6; ++nt) {
        int col = wn + 8 * nt + 2 * (lane & 3);
        float b0 = bias[col], b1 = bias[col + 1];
        int cd = colbase + col;
        #pragma unroll
        for (int mt = 0; mt < 2; ++mt) {
            int r0 = wm + 16 * mt + (lane >> 2);
            *(__half2*)&dst[r0 * ASTR + cd] =
                __floats2half2_rn(acc[mt][nt][0] + b0, acc[mt][nt][1] + b1);
            *(__half2*)&dst[(r0 + 8) * ASTR + cd] =
                __floats2half2_rn(acc[mt][nt][2] + b0, acc[mt][nt][3] + b1);
        }
    }
}

// one warp computes a full 64x64 attention for (window, head); O overwrites Q
__device__ __forceinline__ void attn_pair(__half* Qs, const __half* Ks, const __half* Vs,
                                          const float* rel_s, int win, int head,
                                          bool maskY, bool maskX, int lane)
{
    const int w64 = win * 64;
    const int hc  = head * 32;
    const float* rl = rel_s + head * 225;

    // ---- S = Q K^T : 64x64, k=32 ----
    float s[4][8][4];
    #pragma unroll
    for (int mt = 0; mt < 4; ++mt)
        #pragma unroll
        for (int nt = 0; nt < 8; ++nt)
            #pragma unroll
            for (int j = 0; j < 4; ++j) s[mt][nt][j] = 0.f;

    #pragma unroll
    for (int kc = 0; kc < 32; kc += 16) {
        uint32_t qf[4][4], kf[8][2];
        #pragma unroll
        for (int mt = 0; mt < 4; ++mt) {
            uint32_t aa = smem_u32(&Qs[(w64 + 16 * mt + (lane & 15)) * ASTR
                                       + hc + kc + 8 * (lane >> 4)]);
            ldsm4(qf[mt][0], qf[mt][1], qf[mt][2], qf[mt][3], aa);
        }
        #pragma unroll
        for (int g = 0; g < 4; ++g) {
            int m = lane >> 3;
            uint32_t ba = smem_u32(&Ks[(w64 + 16 * g + (lane & 7) + 8 * (m >> 1)) * ASTR
                                       + hc + kc + 8 * (m & 1)]);
            ldsm4(kf[2*g][0], kf[2*g][1], kf[2*g+1][0], kf[2*g+1][1], ba);
        }
        #pragma unroll
        for (int mt = 0; mt < 4; ++mt)
            #pragma unroll
            for (int nt = 0; nt < 8; ++nt)
                mma16816(s[mt][nt], qf[mt], kf[nt]);
    }

    // ---- scale + rel bias + mask; softmax over 64 cols ----
    const int qx0 = 2 * (lane & 3), qx1 = qx0 + 1;
    float inv0[4], inv1[4];
    #pragma unroll
    for (int mt = 0; mt < 4; ++mt) {
        const int r1 = 16 * mt + (lane >> 2), r2 = r1 + 8;
        const int r1y = r1 >> 3, r1x = r1 & 7, r2y = r2 >> 3, r2x = r2 & 7;
        #pragma unroll
        for (int nt = 0; nt < 8; ++nt) {
            bool mY1 = maskY && ((r1y < 4) != (nt < 4));
            bool mY2 = maskY && ((r2y < 4) != (nt < 4));
            bool mX0 = maskX && ((r1x < 4) != (qx0 < 4));   // r1x==r2x pattern differs; compute both
            bool mX1 = maskX && ((r1x < 4) != (qx1 < 4));
            bool mX2 = maskX && ((r2x < 4) != (qx0 < 4));
            bool mX3 = maskX && ((r2x < 4) != (qx1 < 4));
            float v0 = s[mt][nt][0] * SCALE + rl[(r1y - nt + 7) * 15 + (r1x - qx0 + 7)];
            float v1 = s[mt][nt][1] * SCALE + rl[(r1y - nt + 7) * 15 + (r1x - qx1 + 7)];
            float v2 = s[mt][nt][2] * SCALE + rl[(r2y - nt + 7) * 15 + (r2x - qx0 + 7)];
            float v3 = s[mt][nt][3] * SCALE + rl[(r2y - nt + 7) * 15 + (r2x - qx1 + 7)];
            s[mt][nt][0] = (mY1 || mX0) ? -1e30f : v0;
            s[mt][nt][1] = (mY1 || mX1) ? -1e30f : v1;
            s[mt][nt][2] = (mY2 || mX2) ? -1e30f : v2;
            s[mt][nt][3] = (mY2 || mX3) ? -1e30f : v3;
        }
        float m0v = -1e30f, m1v = -1e30f;
        #pragma unroll
        for (int nt = 0; nt < 8; ++nt) {
            m0v = fmaxf(m0v, fmaxf(s[mt][nt][0], s[mt][nt][1]));
            m1v = fmaxf(m1v, fmaxf(s[mt][nt][2], s[mt][nt][3]));
        }
        m0v = fmaxf(m0v, __shfl_xor_sync(0xffffffffu, m0v, 1));
        m0v = fmaxf(m0v, __shfl_xor_sync(0xffffffffu, m0v, 2));
        m1v = fmaxf(m1v, __shfl_xor_sync(0xffffffffu, m1v, 1));
        m1v = fmaxf(m1v, __shfl_xor_sync(0xffffffffu, m1v, 2));
        float s0 = 0.f, s1 = 0.f;
        #pragma unroll
        for (int nt = 0; nt < 8; ++nt) {
            s[mt][nt][0] = __expf(s[mt][nt][0] - m0v); s0 += s[mt][nt][0];
            s[mt][nt][1] = __expf(s[mt][nt][1] - m0v); s0 += s[mt][nt][1];
            s[mt][nt][2] = __expf(s[mt][nt][2] - m1v); s1 += s[mt][nt][2];
            s[mt][nt][3] = __expf(s[mt][nt][3] - m1v); s1 += s[mt][nt][3];
        }
        s0 += __shfl_xor_sync(0xffffffffu, s0, 1);
        s0 += __shfl_xor_sync(0xffffffffu, s0, 2);
        s1 += __shfl_xor_sync(0xffffffffu, s1, 1);
        s1 += __shfl_xor_sync(0xffffffffu, s1, 2);
        inv0[mt] = 1.f / s0; inv1[mt] = 1.f / s1;
    }

    // ---- P -> fp16 A-fragments ----
    uint32_t p[4][4][4];
    #pragma unroll
    for (int mt = 0; mt < 4; ++mt)
        #pragma unroll
        for (int kc = 0; kc < 4; ++kc) {
            __half2 h0 = __floats2half2_rn(s[mt][2*kc  ][0] * inv0[mt], s[mt][2*kc  ][1] * inv0[mt]);
            __half2 h1 = __floats2half2_rn(s[mt][2*kc  ][2] * inv1[mt], s[mt][2*kc  ][3] * inv1[mt]);
            __half2 h2 = __floats2half2_rn(s[mt][2*kc+1][0] * inv0[mt], s[mt][2*kc+1][1] * inv0[mt]);
            __half2 h3 = __floats2half2_rn(s[mt][2*kc+1][2] * inv1[mt], s[mt][2*kc+1][3] * inv1[mt]);
            p[mt][kc][0] = *(uint32_t*)&h0; p[mt][kc][1] = *(uint32_t*)&h1;
            p[mt][kc][2] = *(uint32_t*)&h2; p[mt][kc][3] = *(uint32_t*)&h3;
        }

    // ---- O = P V : 64x32, k=64 ----
    float o[4][4][4];
    #pragma unroll
    for (int mt = 0; mt < 4; ++mt)
        #pragma unroll
        for (int n = 0; n < 4; ++n)
            #pragma unroll
            for (int j = 0; j < 4; ++j) o[mt][n][j] = 0.f;

    #pragma unroll
    for (int kc = 0; kc < 4; ++kc) {
        uint32_t vf[4][2];
        #pragma unroll
        for (int g = 0; g < 2; ++g) {
            int m = lane >> 3;
            uint32_t va = smem_u32(&Vs[(w64 + 16 * kc + (lane & 7) + 8 * (m & 1)) * ASTR
                                       + hc + 16 * g + 8 * (m >> 1)]);
            ldsm4t(vf[2*g][0], vf[2*g][1], vf[2*g+1][0], vf[2*g+1][1], va);
        }
        #pragma unroll
        for (int mt = 0; mt < 4; ++mt)
            #pragma unroll
            for (int n = 0; n < 4; ++n)
                mma16816(o[mt][n], p[mt][kc], vf[n]);
    }

    // ---- O overwrites Q region (same warp owned Q; fully consumed) ----
    #pragma unroll
    for (int mt = 0; mt < 4; ++mt) {
        int r1 = w64 + 16 * mt + (lane >> 2), r2 = r1 + 8;
        #pragma unroll
        for (int n = 0; n < 4; ++n) {
            int cc = hc + 8 * n + 2 * (lane & 3);
            *(__half2*)&Qs[r1 * ASTR + cc] = __floats2half2_rn(o[mt][n][0], o[mt][n][1]);
            *(__half2*)&Qs[r2 * ASTR + cc] = __floats2half2_rn(o[mt][n][2], o[mt][n][3]);
        }
    }
}

// ---------------------------------------------------------------------------
// The fused kernel. grid(1024), 256 threads.
// smem: Qs(128x200) Ks Vs Bs(96x200) rel(1350 f)
// ---------------------------------------------------------------------------
#define SM_Q 0
#define SM_K 25600
#define SM_V 51200
#define SM_B 76800
#define SM_R 96000            // as half-index; floats after this
#define FUSED_SMEM (96000 * 2 + 5400)

__global__ __launch_bounds__(256)
void fused_kernel(const float* __restrict__ xin, const float* __restrict__ bin,
                  const float* __restrict__ b_qkv, const float* __restrict__ b_qkv_b,
                  const float* __restrict__ rel, const float* __restrict__ b_out,
                  float* __restrict__ out)
{
    extern __shared__ __half sm[];
    __half* Qs  = sm + SM_Q;
    __half* Ks  = sm + SM_K;
    __half* Vs  = sm + SM_V;
    __half* Bsm = sm + SM_B;
    float*  rel_s = (float*)(sm + SM_R);

    const int tid = threadIdx.x, warp = tid >> 5, lane = tid & 31;
    const int m0 = blockIdx.x * 128;
    const int wm = (warp >> 1) * 32, wn = (warp & 1) * 48;

    for (int i = tid; i < 1350; i += 256) rel_s[i] = rel[i];

    // ---- stage x, compute K and V ----
    stage_input(xin, Qs, m0, tid);
    __syncthreads();

    #pragma unroll
    for (int r = 0; r < 2; ++r) {                 // r=0 -> K, r=1 -> V
        __half* Dst = r ? Vs : Ks;
        #pragma unroll
        for (int g = 0; g < 2; ++g) {
            load_w(Bsm, gw_qkv + (size_t)(192 + r * 192 + g * 96) * C, tid);
            __syncthreads();
            float acc[2][6][4] = {};
            gemm_group(Qs, Bsm, lane, wm, wn, acc);
            epi_smem(Dst, g * 96, b_qkv + 192 + r * 192 + g * 96, lane, wm, wn, acc);
            __syncthreads();
        }
    }

    // ---- stage b, compute Q (both groups in registers, then in-place) ----
    stage_input(bin, Qs, m0, tid);
    __syncthreads();
    {
        float accA[2][6][4] = {}, accB[2][6][4] = {};
        load_w(Bsm, gw_qkvb, tid);
        __syncthreads();
        gemm_group(Qs, Bsm, lane, wm, wn, accA);
        __syncthreads();
        load_w(Bsm, gw_qkvb + (size_t)96 * C, tid);
        __syncthreads();
        gemm_group(Qs, Bsm, lane, wm, wn, accB);
        __syncthreads();                          // all reads of Qs done
        epi_smem(Qs, 0,  b_qkv_b,      lane, wm, wn, accA);
        epi_smem(Qs, 96, b_qkv_b + 96, lane, wm, wn, accB);
    }
    __syncthreads();

    // ---- attention: 12 (window, head) pairs, 1 warp each ----
    {
        const int gw0 = blockIdx.x * 2;
        for (int pp = warp; pp < 12; pp += 8) {
            int win = (pp >= 6) ? 1 : 0;
            int head = pp - win * 6;
            int wimg = (gw0 + win) & 1023;
            attn_pair(Qs, Ks, Vs, rel_s, win, head,
                      (wimg >> 5) == 31, (wimg & 31) == 31, lane);
        }
    }
    __syncthreads();

    // ---- output projection + scatter ----
    int orow[2][2];
    #pragma unroll
    for (int mt = 0; mt < 2; ++mt) {
        int r0 = m0 + wm + 16 * mt + (lane >> 2);
        orow[mt][0] = tok_to_pix_row(r0);
        orow[mt][1] = tok_to_pix_row(r0 + 8);
    }
    #pragma unroll
    for (int g = 0; g < 2; ++g) {
        load_w(Bsm, gw_out + (size_t)g * 96 * C, tid);
        __syncthreads();
        float acc[2][6][4] = {};
        gemm_group(Qs, Bsm, lane, wm, wn, acc);
        #pragma unroll
        for (int nt = 0; nt < 6; ++nt) {
            int colg = g * 96 + wn + 8 * nt + 2 * (lane & 3);
            float b0 = b_out[colg], b1 = b_out[colg + 1];
            #pragma unroll
            for (int mt = 0; mt < 2; ++mt) {
                *(float2*)(out + orow[mt][0] + colg) =
                    make_float2(acc[mt][nt][0] + b0, acc[mt][nt][1] + b1);
                *(float2*)(out + orow[mt][1] + colg) =
                    make_float2(acc[mt][nt][2] + b0, acc[mt][nt][3] + b1);
            }
        }
        __syncthreads();
    }
}

// ---------------------------------------------------------------------------
extern "C" void kernel_launch(void* const* d_in, const int* in_sizes, int n_in,
                              void* d_out, int out_size)
{
    const float* x        = (const float*)d_in[0];
    const float* b        = (const float*)d_in[1];
    const float* w_qkv    = (const float*)d_in[2];
    const float* b_qkv    = (const float*)d_in[3];
    const float* w_qkv_b  = (const float*)d_in[4];
    const float* b_qkv_b  = (const float*)d_in[5];
    const float* rel      = (const float*)d_in[6];
    const float* w_out    = (const float*)d_in[7];
    const float* b_out    = (const float*)d_in[8];
    float* out = (float*)d_out;

    cudaFuncSetAttribute(fused_kernel, cudaFuncAttributeMaxDynamicSharedMemorySize,
                         FUSED_SMEM);

    prep_kernel<<<432, 256>>>(w_qkv, w_qkv_b, w_out);
    fused_kernel<<<1024, 256, FUSED_SMEM>>>(x, b, b_qkv, b_qkv_b, rel, b_out, out);
}